// round 8
// baseline (speedup 1.0000x reference)
#include <cuda_runtime.h>
#include <cuda_fp16.h>

#define FEAT 4096
#define TT   2048
#define ODIM 512
#define NCTA 148
#define NTHREADS 1024
#define SMEMB (28 * FEAT * 2)   // 28 rows of fp16 weights = 229376 bytes
#define SENT 0x7F7F7F7Fu        // fp16 NaN pair sentinel

// Static device scratch (no runtime allocation allowed)
__device__ __half d_Wh[(size_t)FEAT * FEAT];      // fp16 W_res, 33.5 MB
__device__ __half d_G[(size_t)(TT + 1) * FEAT];   // feats history (fp16), 16.8 MB

// ---------------------------------------------------------------------------
// fp32 -> fp16 weight conversion
// ---------------------------------------------------------------------------
__global__ void convert_kernel(const float* __restrict__ W) {
    size_t n = (size_t)FEAT * FEAT / 4;
    for (size_t i = blockIdx.x * (size_t)blockDim.x + threadIdx.x; i < n;
         i += (size_t)gridDim.x * blockDim.x) {
        float4 v = reinterpret_cast<const float4*>(W)[i];
        __half2 h0 = __floats2half2_rn(v.x, v.y);
        __half2 h1 = __floats2half2_rn(v.z, v.w);
        uint2 u;
        u.x = *reinterpret_cast<unsigned*>(&h0);
        u.y = *reinterpret_cast<unsigned*>(&h1);
        reinterpret_cast<uint2*>(d_Wh)[i] = u;
    }
}

// ---------------------------------------------------------------------------
__device__ __forceinline__ uint4 ld_vol4(const uint4* p) {
    uint4 v;
    asm volatile("ld.volatile.global.v4.u32 {%0,%1,%2,%3}, [%4];"
                 : "=r"(v.x), "=r"(v.y), "=r"(v.z), "=r"(v.w) : "l"(p) : "memory");
    return v;
}
__device__ __forceinline__ bool valid4(uint4 u) {
    return (u.x != SENT) & (u.y != SENT) & (u.z != SENT) & (u.w != SENT);
}
__device__ __forceinline__ void h8_to_f(uint4 u, float* o) {
    __half2* h = reinterpret_cast<__half2*>(&u);
    float2 a = __half22float2(h[0]);
    float2 b = __half22float2(h[1]);
    float2 c = __half22float2(h[2]);
    float2 d = __half22float2(h[3]);
    o[0] = a.x; o[1] = a.y; o[2] = b.x; o[3] = b.y;
    o[4] = c.x; o[5] = c.y; o[6] = d.x; o[7] = d.y;
}

// ---------------------------------------------------------------------------
// Persistent recurrence kernel, pure dataflow sync.
// 148 CTAs: first 124 own 28 rows, last 24 own 26 rows (all even-aligned).
// Warp layout: 32 warps = 4 row-groups x 8 k-groups.
//   warp w: rg = w&3 (rows rg*7 .. rg*7+6), kg = w>>2 (k in [kg*512, +512))
//   lane l: 16 halves at cb = kg*512 + l*8 and cb+256.
// Rows rbeg, rbeg+1 of each warp are register-resident (loaded once).
// Sync: consumers poll their own feature words against the NaN sentinel;
// the successful poll load IS the data (no fences, no counters, no bars).
// ---------------------------------------------------------------------------
extern "C" __global__ void __launch_bounds__(NTHREADS, 1)
rc_kernel(const float* __restrict__ x) {
    extern __shared__ __half sW[];            // [nrows][FEAT]
    __shared__ float sPart[2][32][9];         // parity double-buffer, stride 9

    const int b   = blockIdx.x;
    const int tid = threadIdx.x;

    // Row distribution: 124 CTAs x 28 + 24 CTAs x 26 = 4096, all r0 even.
    int r0, nrows;
    if (b < 124) { r0 = b * 28;                nrows = 28; }
    else         { r0 = 3472 + (b - 124) * 26; nrows = 26; }

    // Stage W slice into SMEM (once)
    {
        const uint4* wg = reinterpret_cast<const uint4*>(d_Wh + (size_t)r0 * FEAT);
        uint4* ws = reinterpret_cast<uint4*>(sW);
        int nv = nrows * FEAT / 8;
        for (int i = tid; i < nv; i += NTHREADS) ws[i] = wg[i];
    }
    __syncthreads();

    const int w    = tid >> 5;
    const int lane = tid & 31;
    const int rg   = w & 3;
    const int kg   = w >> 2;
    const int rbeg = rg * 7;
    const int rend = min(rbeg + 7, nrows);
    const int cb   = kg * 512 + lane * 8;

    // Register-resident weights for this warp's first two rows
    __half2 wreg[2][8];
    #pragma unroll
    for (int j = 0; j < 2; ++j) {
        const __half* wr = sW + (size_t)(rbeg + j) * FEAT + cb;
        uint4 wa = *reinterpret_cast<const uint4*>(wr);
        uint4 wb = *reinterpret_cast<const uint4*>(wr + 256);
        __half2* pa = reinterpret_cast<__half2*>(&wa);
        __half2* pb = reinterpret_cast<__half2*>(&wb);
        #pragma unroll
        for (int q = 0; q < 4; ++q) { wreg[j][q] = pa[q]; wreg[j][4 + q] = pb[q]; }
    }

    for (int t = 0; t < TT; ++t) {
        // x[:, t] for warp 0's final stage (independent of feats)
        float xv = 0.f;
        if (w == 0 && lane < nrows) xv = __ldg(&x[(size_t)(r0 + lane) * TT + t]);

        // Poll this lane's 16 feature halves until written (data-carrying sync)
        const uint4* p0 = reinterpret_cast<const uint4*>(d_G + (size_t)t * FEAT + cb);
        const uint4* p1 = reinterpret_cast<const uint4*>(d_G + (size_t)t * FEAT + cb + 256);
        uint4 fa, fb;
        do { fa = ld_vol4(p0); } while (!valid4(fa));
        do { fb = ld_vol4(p1); } while (!valid4(fb));

        __half2 fh[8];
        {
            __half2* pa = reinterpret_cast<__half2*>(&fa);
            __half2* pb = reinterpret_cast<__half2*>(&fb);
            #pragma unroll
            for (int q = 0; q < 4; ++q) { fh[q] = pa[q]; fh[4 + q] = pb[q]; }
        }

        float acc[7];

        // Rows 0,1: register-resident weights
        #pragma unroll
        for (int j = 0; j < 2; ++j) {
            __half2 a0 = __hmul2(wreg[j][0], fh[0]);
            __half2 a1 = __hmul2(wreg[j][1], fh[1]);
            a0 = __hfma2(wreg[j][2], fh[2], a0);
            a1 = __hfma2(wreg[j][3], fh[3], a1);
            a0 = __hfma2(wreg[j][4], fh[4], a0);
            a1 = __hfma2(wreg[j][5], fh[5], a1);
            a0 = __hfma2(wreg[j][6], fh[6], a0);
            a1 = __hfma2(wreg[j][7], fh[7], a1);
            __half2 s2 = __hadd2(a0, a1);
            acc[j] = __low2float(s2) + __high2float(s2);
        }
        // Rows 2..6: weights from SMEM
        #pragma unroll
        for (int j = 2; j < 7; ++j) {
            acc[j] = 0.f;
            int r = rbeg + j;
            if (r < rend) {
                const __half* wr = sW + (size_t)r * FEAT + cb;
                uint4 wa = *reinterpret_cast<const uint4*>(wr);
                uint4 wb = *reinterpret_cast<const uint4*>(wr + 256);
                __half2* wha = reinterpret_cast<__half2*>(&wa);
                __half2* whb = reinterpret_cast<__half2*>(&wb);
                __half2 a0 = __hmul2(wha[0], fh[0]);
                __half2 a1 = __hmul2(wha[1], fh[1]);
                a0 = __hfma2(wha[2], fh[2], a0);
                a1 = __hfma2(wha[3], fh[3], a1);
                a0 = __hfma2(whb[0], fh[4], a0);
                a1 = __hfma2(whb[1], fh[5], a1);
                a0 = __hfma2(whb[2], fh[6], a0);
                a1 = __hfma2(whb[3], fh[7], a1);
                __half2 s2 = __hadd2(a0, a1);
                acc[j] = __low2float(s2) + __high2float(s2);
            }
        }

        // Warp reduction (fp32) and partial store (parity buffer)
        const int par = t & 1;
        #pragma unroll
        for (int j = 0; j < 7; ++j) {
            float v = acc[j];
            v += __shfl_down_sync(0xFFFFFFFFu, v, 16);
            v += __shfl_down_sync(0xFFFFFFFFu, v, 8);
            v += __shfl_down_sync(0xFFFFFFFFu, v, 4);
            v += __shfl_down_sync(0xFFFFFFFFu, v, 2);
            v += __shfl_down_sync(0xFFFFFFFFu, v, 1);
            if (lane == 0 && rbeg + j < rend) sPart[par][rbeg + j][kg] = v;
        }
        __syncthreads();   // the ONLY per-step CTA barrier

        // Warp 0: final sums, clamp, pack row-pairs, store as atomic u32.
        if (w == 0) {
            float s = 0.f;
            #pragma unroll
            for (int k = 0; k < 8; ++k) s += sPart[par][lane][k];
            s += xv;
            s = fminf(fmaxf(s, -1.f), 1.f);
            float shi = __shfl_down_sync(0xFFFFFFFFu, s, 1);
            if (((lane & 1) == 0) && lane < nrows) {
                __half2 hp = __floats2half2_rn(s, shi);
                unsigned word = *reinterpret_cast<unsigned*>(&hp);
                unsigned* dst = reinterpret_cast<unsigned*>(d_G)
                              + (((size_t)(t + 1) * FEAT + r0 + lane) >> 1);
                *dst = word;
            }
        }
        // No trailing barrier: sPart parity + dataflow ordering make it safe.
    }
}

// ---------------------------------------------------------------------------
// Readout GEMM: out[o][t] = sum_f w_out[o][f] * G[t+1][f]   (G is fp16)
// ---------------------------------------------------------------------------
__global__ void __launch_bounds__(256)
out_gemm(const float* __restrict__ wout, float* __restrict__ out) {
    __shared__ float As[32][65];
    __shared__ float Bs[32][65];

    const int t0 = blockIdx.x * 64;
    const int o0 = blockIdx.y * 64;
    const int tid = threadIdx.x;
    const int tx = tid & 15, ty = tid >> 4;

    float c[4][4];
    #pragma unroll
    for (int p = 0; p < 4; ++p)
        #pragma unroll
        for (int q = 0; q < 4; ++q) c[p][q] = 0.f;

    for (int k0 = 0; k0 < FEAT; k0 += 32) {
        #pragma unroll
        for (int it = 0; it < 2; ++it) {
            int idx = it * 256 + tid;
            int i  = idx >> 3;
            int kv = (idx & 7) * 4;
            float4 v = *reinterpret_cast<const float4*>(
                &wout[(size_t)(o0 + i) * FEAT + k0 + kv]);
            As[kv + 0][i] = v.x; As[kv + 1][i] = v.y;
            As[kv + 2][i] = v.z; As[kv + 3][i] = v.w;
        }
        {
            int j  = tid >> 2;
            int kv = (tid & 3) * 8;
            uint4 u = *reinterpret_cast<const uint4*>(
                &d_G[(size_t)(t0 + j + 1) * FEAT + k0 + kv]);
            float bf[8];
            h8_to_f(u, bf);
            #pragma unroll
            for (int q = 0; q < 8; ++q) Bs[kv + q][j] = bf[q];
        }
        __syncthreads();

        #pragma unroll
        for (int kk = 0; kk < 32; ++kk) {
            float a[4], bb[4];
            #pragma unroll
            for (int p = 0; p < 4; ++p) a[p] = As[kk][ty * 4 + p];
            #pragma unroll
            for (int q = 0; q < 4; ++q) bb[q] = Bs[kk][tx * 4 + q];
            #pragma unroll
            for (int p = 0; p < 4; ++p)
                #pragma unroll
                for (int q = 0; q < 4; ++q)
                    c[p][q] = fmaf(a[p], bb[q], c[p][q]);
        }
        __syncthreads();
    }

    #pragma unroll
    for (int p = 0; p < 4; ++p)
        #pragma unroll
        for (int q = 0; q < 4; ++q)
            out[(size_t)(o0 + ty * 4 + p) * TT + t0 + tx * 4 + q] = c[p][q];
}

// ---------------------------------------------------------------------------
extern "C" void kernel_launch(void* const* d_in, const int* in_sizes, int n_in,
                              void* d_out, int out_size) {
    const float* x    = (const float*)d_in[0];   // [4096, 2048]
    const float* Wres = (const float*)d_in[1];   // [4096, 4096]
    const float* wout = (const float*)d_in[2];   // [512, 4096]
    float* out = (float*)d_out;                  // [512, 2048]

    cudaFuncSetAttribute(rc_kernel, cudaFuncAttributeMaxDynamicSharedMemorySize, SMEMB);

    void* gp = nullptr;
    cudaGetSymbolAddress(&gp, d_G);
    // Sentinel-fill the whole history (0x7F7F = fp16 NaN), then zero feats_0.
    cudaMemsetAsync(gp, 0x7F, (size_t)(TT + 1) * FEAT * sizeof(__half));
    cudaMemsetAsync(gp, 0, FEAT * sizeof(__half));

    convert_kernel<<<1024, 256>>>(Wres);
    rc_kernel<<<NCTA, NTHREADS, SMEMB>>>(x);
    out_gemm<<<dim3(TT / 64, ODIM / 64), 256>>>(wout, out);
}

// round 9
// speedup vs baseline: 2.9610x; 2.9610x over previous
#include <cuda_runtime.h>
#include <cuda_fp16.h>

#define FEAT 4096
#define TT   2048
#define ODIM 512
#define NCTA 148
#define NTHREADS 1024
#define SMEMB (28 * FEAT * 2)   // 28 rows of fp16 weights = 229376 bytes

// Static device scratch (no runtime allocation allowed)
__device__ __half   d_Wh[(size_t)FEAT * FEAT];      // fp16 W_res, 33.5 MB
__device__ __half   d_G[(size_t)(TT + 1) * FEAT];   // feats history (fp16), 16.8 MB
__device__ float    d_xT[(size_t)TT * FEAT];        // transposed x, 32 MB
__device__ unsigned d_cnt[TT];                      // per-step arrival counters

// ---------------------------------------------------------------------------
// fp32 -> fp16 weight conversion
// ---------------------------------------------------------------------------
__global__ void convert_kernel(const float* __restrict__ W) {
    size_t n = (size_t)FEAT * FEAT / 4;
    for (size_t i = blockIdx.x * (size_t)blockDim.x + threadIdx.x; i < n;
         i += (size_t)gridDim.x * blockDim.x) {
        float4 v = reinterpret_cast<const float4*>(W)[i];
        __half2 h0 = __floats2half2_rn(v.x, v.y);
        __half2 h1 = __floats2half2_rn(v.z, v.w);
        uint2 u;
        u.x = *reinterpret_cast<unsigned*>(&h0);
        u.y = *reinterpret_cast<unsigned*>(&h1);
        reinterpret_cast<uint2*>(d_Wh)[i] = u;
    }
}

// ---------------------------------------------------------------------------
// x transpose: x[f][t] -> xT[t][f]  (32x32 tiles)
// ---------------------------------------------------------------------------
__global__ void xpose_kernel(const float* __restrict__ x) {
    __shared__ float tile[32][33];
    int t0 = blockIdx.x * 32;     // t tile
    int f0 = blockIdx.y * 32;     // f tile
    int tx = threadIdx.x, ty = threadIdx.y;  // 32 x 8
    #pragma unroll
    for (int r = 0; r < 32; r += 8)
        tile[ty + r][tx] = x[(size_t)(f0 + ty + r) * TT + t0 + tx];
    __syncthreads();
    #pragma unroll
    for (int r = 0; r < 32; r += 8)
        d_xT[(size_t)(t0 + ty + r) * FEAT + f0 + tx] = tile[tx][ty + r];
}

// ---------------------------------------------------------------------------
// Sync primitives (proven: single counter, release-red + tid0 acquire-poll)
// ---------------------------------------------------------------------------
__device__ __forceinline__ unsigned ld_acq(const unsigned* p) {
    unsigned v;
    asm volatile("ld.acquire.gpu.global.u32 %0, [%1];" : "=r"(v) : "l"(p) : "memory");
    return v;
}
__device__ __forceinline__ void red_rel_add1(unsigned* p) {
    asm volatile("red.release.gpu.global.add.u32 [%0], 1;" :: "l"(p) : "memory");
}

__device__ __forceinline__ void h8_to_f(uint4 u, float* o) {
    __half2* h = reinterpret_cast<__half2*>(&u);
    float2 a = __half22float2(h[0]);
    float2 b = __half22float2(h[1]);
    float2 c = __half22float2(h[2]);
    float2 d = __half22float2(h[3]);
    o[0] = a.x; o[1] = a.y; o[2] = b.x; o[3] = b.y;
    o[4] = c.x; o[5] = c.y; o[6] = d.x; o[7] = d.y;
}

// ---------------------------------------------------------------------------
// Persistent recurrence kernel: 148 CTAs, each owns <=28 rows of W.
// Rows rbeg, rbeg+1 of each warp register-resident; rows 2..6 from SMEM.
// Hot loop: HFMA2. Sync: R5-proven counter scheme, 2 barriers/step total.
// Warp layout: 32 warps = 4 row-groups x 8 k-groups.
// ---------------------------------------------------------------------------
extern "C" __global__ void __launch_bounds__(NTHREADS, 1)
rc_kernel() {
    extern __shared__ __half sW[];            // [nrows][FEAT]
    __shared__ float sPart[2][28][9];         // parity-buffered, stride 9

    const int b   = blockIdx.x;
    const int tid = threadIdx.x;

    // Row distribution: first 100 CTAs get 28 rows, last 48 get 27 (=4096).
    int r0, nrows;
    if (b < 100) { r0 = b * 28;                nrows = 28; }
    else         { r0 = 2800 + (b - 100) * 27; nrows = 27; }

    // Stage W slice into SMEM (once)
    {
        const uint4* wg = reinterpret_cast<const uint4*>(d_Wh + (size_t)r0 * FEAT);
        uint4* ws = reinterpret_cast<uint4*>(sW);
        int nv = nrows * FEAT / 8;
        for (int i = tid; i < nv; i += NTHREADS) ws[i] = wg[i];
    }
    __syncthreads();

    const int w    = tid >> 5;
    const int lane = tid & 31;
    const int rg   = w & 3;
    const int kg   = w >> 2;
    const int rbeg = rg * 7;
    const int rend = min(rbeg + 7, nrows);
    const int cb   = kg * 512 + lane * 8;

    // Register-resident weights for this warp's first two rows
    __half2 wreg[2][8];
    #pragma unroll
    for (int j = 0; j < 2; ++j) {
        const __half* wr = sW + (size_t)(rbeg + j) * FEAT + cb;
        uint4 wa = *reinterpret_cast<const uint4*>(wr);
        uint4 wb = *reinterpret_cast<const uint4*>(wr + 256);
        __half2* pa = reinterpret_cast<__half2*>(&wa);
        __half2* pb = reinterpret_cast<__half2*>(&wb);
        #pragma unroll
        for (int q = 0; q < 4; ++q) { wreg[j][q] = pa[q]; wreg[j][4 + q] = pb[q]; }
    }

    for (int t = 0; t < TT; ++t) {
        // Coalesced x prefetch (in flight during the poll)
        float xv = 0.f;
        if (tid < nrows) xv = __ldg(&d_xT[(size_t)t * FEAT + r0 + tid]);

        if (t > 0) {
            if (tid == 0) {
                while (ld_acq(&d_cnt[t - 1]) < NCTA) { }
            }
            __syncthreads();
        }

        // Load this lane's 16 features as 8 x half2
        const __half* f = d_G + (size_t)t * FEAT;
        uint4 fa = __ldcg(reinterpret_cast<const uint4*>(f + cb));
        uint4 fb = __ldcg(reinterpret_cast<const uint4*>(f + cb + 256));
        __half2 fh[8];
        {
            __half2* pa = reinterpret_cast<__half2*>(&fa);
            __half2* pb = reinterpret_cast<__half2*>(&fb);
            #pragma unroll
            for (int q = 0; q < 4; ++q) { fh[q] = pa[q]; fh[4 + q] = pb[q]; }
        }

        float acc[7];

        // Rows 0,1: register-resident weights
        #pragma unroll
        for (int j = 0; j < 2; ++j) {
            __half2 a0 = __hmul2(wreg[j][0], fh[0]);
            __half2 a1 = __hmul2(wreg[j][1], fh[1]);
            a0 = __hfma2(wreg[j][2], fh[2], a0);
            a1 = __hfma2(wreg[j][3], fh[3], a1);
            a0 = __hfma2(wreg[j][4], fh[4], a0);
            a1 = __hfma2(wreg[j][5], fh[5], a1);
            a0 = __hfma2(wreg[j][6], fh[6], a0);
            a1 = __hfma2(wreg[j][7], fh[7], a1);
            __half2 s2 = __hadd2(a0, a1);
            acc[j] = __low2float(s2) + __high2float(s2);
        }
        // Rows 2..6: weights from SMEM
        #pragma unroll
        for (int j = 2; j < 7; ++j) {
            acc[j] = 0.f;
            int r = rbeg + j;
            if (r < rend) {
                const __half* wr = sW + (size_t)r * FEAT + cb;
                uint4 wa = *reinterpret_cast<const uint4*>(wr);
                uint4 wb = *reinterpret_cast<const uint4*>(wr + 256);
                __half2* wha = reinterpret_cast<__half2*>(&wa);
                __half2* whb = reinterpret_cast<__half2*>(&wb);
                __half2 a0 = __hmul2(wha[0], fh[0]);
                __half2 a1 = __hmul2(wha[1], fh[1]);
                a0 = __hfma2(wha[2], fh[2], a0);
                a1 = __hfma2(wha[3], fh[3], a1);
                a0 = __hfma2(whb[0], fh[4], a0);
                a1 = __hfma2(whb[1], fh[5], a1);
                a0 = __hfma2(whb[2], fh[6], a0);
                a1 = __hfma2(whb[3], fh[7], a1);
                __half2 s2 = __hadd2(a0, a1);
                acc[j] = __low2float(s2) + __high2float(s2);
            }
        }

        // Warp reduction (fp32) + partial store into parity buffer
        const int par = t & 1;
        #pragma unroll
        for (int j = 0; j < 7; ++j) {
            float v = acc[j];
            v += __shfl_down_sync(0xFFFFFFFFu, v, 16);
            v += __shfl_down_sync(0xFFFFFFFFu, v, 8);
            v += __shfl_down_sync(0xFFFFFFFFu, v, 4);
            v += __shfl_down_sync(0xFFFFFFFFu, v, 2);
            v += __shfl_down_sync(0xFFFFFFFFu, v, 1);
            if (lane == 0 && rbeg + j < rend) sPart[par][rbeg + j][kg] = v;
        }
        __syncthreads();

        // Warp 0: final sums, clamp, store slice, warp-sync, release.
        // (stores + red all in warp 0 -> __syncwarp suffices; sPart reuse is
        //  protected by the next step's post-poll __syncthreads, which warp 0
        //  only reaches after this read.)
        if (w == 0) {
            if (lane < nrows) {
                float s = 0.f;
                #pragma unroll
                for (int k = 0; k < 8; ++k) s += sPart[par][lane][k];
                s += xv;
                s = fminf(fmaxf(s, -1.f), 1.f);
                d_G[(size_t)(t + 1) * FEAT + r0 + lane] = __float2half_rn(s);
            }
            __syncwarp();
            if (lane == 0) red_rel_add1(&d_cnt[t]);
        }
    }
}

// ---------------------------------------------------------------------------
// Readout GEMM: out[o][t] = sum_f w_out[o][f] * G[t+1][f]   (G is fp16)
// ---------------------------------------------------------------------------
__global__ void __launch_bounds__(256)
out_gemm(const float* __restrict__ wout, float* __restrict__ out) {
    __shared__ float As[32][65];
    __shared__ float Bs[32][65];

    const int t0 = blockIdx.x * 64;
    const int o0 = blockIdx.y * 64;
    const int tid = threadIdx.x;
    const int tx = tid & 15, ty = tid >> 4;

    float c[4][4];
    #pragma unroll
    for (int p = 0; p < 4; ++p)
        #pragma unroll
        for (int q = 0; q < 4; ++q) c[p][q] = 0.f;

    for (int k0 = 0; k0 < FEAT; k0 += 32) {
        #pragma unroll
        for (int it = 0; it < 2; ++it) {
            int idx = it * 256 + tid;
            int i  = idx >> 3;
            int kv = (idx & 7) * 4;
            float4 v = *reinterpret_cast<const float4*>(
                &wout[(size_t)(o0 + i) * FEAT + k0 + kv]);
            As[kv + 0][i] = v.x; As[kv + 1][i] = v.y;
            As[kv + 2][i] = v.z; As[kv + 3][i] = v.w;
        }
        {
            int j  = tid >> 2;
            int kv = (tid & 3) * 8;
            uint4 u = *reinterpret_cast<const uint4*>(
                &d_G[(size_t)(t0 + j + 1) * FEAT + k0 + kv]);
            float bf[8];
            h8_to_f(u, bf);
            #pragma unroll
            for (int q = 0; q < 8; ++q) Bs[kv + q][j] = bf[q];
        }
        __syncthreads();

        #pragma unroll
        for (int kk = 0; kk < 32; ++kk) {
            float a[4], bb[4];
            #pragma unroll
            for (int p = 0; p < 4; ++p) a[p] = As[kk][ty * 4 + p];
            #pragma unroll
            for (int q = 0; q < 4; ++q) bb[q] = Bs[kk][tx * 4 + q];
            #pragma unroll
            for (int p = 0; p < 4; ++p)
                #pragma unroll
                for (int q = 0; q < 4; ++q)
                    c[p][q] = fmaf(a[p], bb[q], c[p][q]);
        }
        __syncthreads();
    }

    #pragma unroll
    for (int p = 0; p < 4; ++p)
        #pragma unroll
        for (int q = 0; q < 4; ++q)
            out[(size_t)(o0 + ty * 4 + p) * TT + t0 + tx * 4 + q] = c[p][q];
}

// ---------------------------------------------------------------------------
extern "C" void kernel_launch(void* const* d_in, const int* in_sizes, int n_in,
                              void* d_out, int out_size) {
    const float* x    = (const float*)d_in[0];   // [4096, 2048]
    const float* Wres = (const float*)d_in[1];   // [4096, 4096]
    const float* wout = (const float*)d_in[2];   // [512, 4096]
    float* out = (float*)d_out;                  // [512, 2048]

    cudaFuncSetAttribute(rc_kernel, cudaFuncAttributeMaxDynamicSharedMemorySize, SMEMB);

    void* cntp = nullptr;
    void* gp   = nullptr;
    cudaGetSymbolAddress(&cntp, d_cnt);
    cudaGetSymbolAddress(&gp, d_G);
    cudaMemsetAsync(cntp, 0, TT * sizeof(unsigned));   // reset step counters
    cudaMemsetAsync(gp, 0, FEAT * sizeof(__half));     // feats_0 = 0 (fp16)

    convert_kernel<<<1024, 256>>>(Wres);
    xpose_kernel<<<dim3(TT / 32, FEAT / 32), dim3(32, 8)>>>(x);
    rc_kernel<<<NCTA, NTHREADS, SMEMB>>>();
    out_gemm<<<dim3(TT / 64, ODIM / 64), 256>>>(wout, out);
}